// round 2
// baseline (speedup 1.0000x reference)
#include <cuda_runtime.h>

// Shapes (fixed for this problem)
#define B_ 32
#define S_ 128
#define E_ 512
#define F_ 2048
#define KT 16        // K-tile depth
#define KSPLIT 4     // split-K for GEMM2

// Scratch (device globals: allocation-free)
// g_H layout: [s][f][b]  (b contiguous -> GEMM2 A-tile loads are coalesced)
__device__ float g_H[(size_t)S_ * F_ * B_];
// g_Yp layout: [kp][s][b][e] (e contiguous -> LN kernel reads vectorized)
__device__ float g_Yp[(size_t)KSPLIT * S_ * B_ * E_];

// ---------------------------------------------------------------------------
// GEMM1: H[s][f][b] = sum_e x[b][s][e] * W1[s][e][f] + b1[s][f]
// grid (F_/512, S_), 256 threads. CTA tile: M=32 (b), N=512 (f), K=E_=512.
// Thread tile 8x8 (tm in 0..3 covers 32 m, tn in 0..63 covers 512 n).
// ---------------------------------------------------------------------------
__global__ __launch_bounds__(256, 2)
void gemm1_kernel(const float* __restrict__ x,
                  const float* __restrict__ W1,
                  const float* __restrict__ b1)
{
    __shared__ float As[KT][B_];      // [k][m]
    __shared__ float Bs[KT][512];     // [k][n]

    const int s   = blockIdx.y;
    const int n0  = blockIdx.x * 512;
    const int tid = threadIdx.x;
    const int tm  = tid >> 6;   // 0..3  -> m base tm*8
    const int tn  = tid & 63;   // 0..63 -> n base tn*8

    float acc[8][8];
#pragma unroll
    for (int i = 0; i < 8; i++)
#pragma unroll
        for (int j = 0; j < 8; j++) acc[i][j] = 0.0f;

    for (int kt = 0; kt < E_ / KT; kt++) {
        const int e0 = kt * KT;

        // Load A tile: x[m][s][e0+k], transpose into As[k][m]. 512 floats.
        if (tid < 128) {
            const int m  = tid >> 2;
            const int k4 = (tid & 3) * 4;
            const float4 v = *(const float4*)&x[((size_t)m * S_ + s) * E_ + e0 + k4];
            As[k4 + 0][m] = v.x;
            As[k4 + 1][m] = v.y;
            As[k4 + 2][m] = v.z;
            As[k4 + 3][m] = v.w;
        }
        // Load B tile: W1[s][e0+row][n0 + c]. 16x512 floats = 2048 float4.
#pragma unroll
        for (int i = 0; i < 8; i++) {
            const int idx = i * 256 + tid;     // 0..2047
            const int row = idx >> 7;          // /128
            const int c4  = (idx & 127) * 4;
            *(float4*)&Bs[row][c4] =
                *(const float4*)&W1[((size_t)s * E_ + e0 + row) * F_ + n0 + c4];
        }
        __syncthreads();

#pragma unroll
        for (int k = 0; k < KT; k++) {
            float a[8], b[8];
#pragma unroll
            for (int i = 0; i < 8; i++) a[i] = As[k][tm * 8 + i];
#pragma unroll
            for (int j = 0; j < 8; j++) b[j] = Bs[k][tn * 8 + j];
#pragma unroll
            for (int i = 0; i < 8; i++)
#pragma unroll
                for (int j = 0; j < 8; j++) acc[i][j] += a[i] * b[j];
        }
        __syncthreads();
    }

    // Epilogue: + b1, store to g_H[s][n][m] (m contiguous).
#pragma unroll
    for (int j = 0; j < 8; j++) {
        const int n  = n0 + tn * 8 + j;
        const float bb = b1[(size_t)s * F_ + n];
        float4 v0, v1;
        v0.x = acc[0][j] + bb; v0.y = acc[1][j] + bb;
        v0.z = acc[2][j] + bb; v0.w = acc[3][j] + bb;
        v1.x = acc[4][j] + bb; v1.y = acc[5][j] + bb;
        v1.z = acc[6][j] + bb; v1.w = acc[7][j] + bb;
        float* dst = &g_H[((size_t)s * F_ + n) * B_ + tm * 8];
        *(float4*)(dst)     = v0;
        *(float4*)(dst + 4) = v1;
    }
}

// ---------------------------------------------------------------------------
// GEMM2 (split-K): Yp[kp][s][b][e] = sum_{f in kp-slice} H[s][f][b]*W2[s][f][e]
// grid (S_, KSPLIT), 256 threads. CTA tile: M=32 (b), N=512 (e), K=512 (f-slice)
// ---------------------------------------------------------------------------
__global__ __launch_bounds__(256, 2)
void gemm2_kernel(const float* __restrict__ W2)
{
    __shared__ float As[KT][B_];      // [k][m]
    __shared__ float Bs[KT][E_];      // [k][n]

    const int s   = blockIdx.x;
    const int kp  = blockIdx.y;
    const int f0b = kp * (F_ / KSPLIT);   // 512-wide K slice
    const int tid = threadIdx.x;
    const int tm  = tid >> 6;
    const int tn  = tid & 63;

    float acc[8][8];
#pragma unroll
    for (int i = 0; i < 8; i++)
#pragma unroll
        for (int j = 0; j < 8; j++) acc[i][j] = 0.0f;

    for (int kt = 0; kt < (F_ / KSPLIT) / KT; kt++) {
        const int f0 = f0b + kt * KT;

        // A tile from g_H[s][f0+row][m] — m contiguous, fully coalesced.
        if (tid < 128) {
            const int row = tid >> 3;           // 16 rows
            const int c4  = (tid & 7) * 4;      // 8 float4 per 32-wide row
            *(float4*)&As[row][c4] =
                *(const float4*)&g_H[((size_t)s * F_ + f0 + row) * B_ + c4];
        }
        // B tile: W2[s][f0+row][c]. 16x512 floats.
#pragma unroll
        for (int i = 0; i < 8; i++) {
            const int idx = i * 256 + tid;
            const int row = idx >> 7;
            const int c4  = (idx & 127) * 4;
            *(float4*)&Bs[row][c4] =
                *(const float4*)&W2[((size_t)s * F_ + f0 + row) * E_ + c4];
        }
        __syncthreads();

#pragma unroll
        for (int k = 0; k < KT; k++) {
            float a[8], b[8];
#pragma unroll
            for (int i = 0; i < 8; i++) a[i] = As[k][tm * 8 + i];
#pragma unroll
            for (int j = 0; j < 8; j++) b[j] = Bs[k][tn * 8 + j];
#pragma unroll
            for (int i = 0; i < 8; i++)
#pragma unroll
                for (int j = 0; j < 8; j++) acc[i][j] += a[i] * b[j];
        }
        __syncthreads();
    }

    // Store partial: Yp[kp][s][m][e], e contiguous per m.
#pragma unroll
    for (int i = 0; i < 8; i++) {
        const int m = tm * 8 + i;
        float4 v0, v1;
        v0.x = acc[i][0]; v0.y = acc[i][1]; v0.z = acc[i][2]; v0.w = acc[i][3];
        v1.x = acc[i][4]; v1.y = acc[i][5]; v1.z = acc[i][6]; v1.w = acc[i][7];
        float* dst = &g_Yp[(((size_t)kp * S_ + s) * B_ + m) * E_ + tn * 8];
        *(float4*)(dst)     = v0;
        *(float4*)(dst + 4) = v1;
    }
}

// ---------------------------------------------------------------------------
// LN kernel: y = sum_kp Yp + b2 + x ; out = LayerNorm(y)*gamma + beta
// grid = B_*S_ blocks, 128 threads, 4 elems (1 float4) per thread.
// ---------------------------------------------------------------------------
__global__ __launch_bounds__(128)
void ln_kernel(const float* __restrict__ x,
               const float* __restrict__ b2,
               const float* __restrict__ gamma,
               const float* __restrict__ beta,
               float* __restrict__ out)
{
    const int blk = blockIdx.x;
    const int b   = blk >> 7;      // /S_
    const int s   = blk & (S_ - 1);
    const int tid = threadIdx.x;
    const int e   = tid * 4;

    float4 y = *(const float4*)&g_Yp[(((size_t)0 * S_ + s) * B_ + b) * E_ + e];
#pragma unroll
    for (int kp = 1; kp < KSPLIT; kp++) {
        const float4 p = *(const float4*)&g_Yp[(((size_t)kp * S_ + s) * B_ + b) * E_ + e];
        y.x += p.x; y.y += p.y; y.z += p.z; y.w += p.w;
    }
    {
        const float4 bb = *(const float4*)&b2[(size_t)s * E_ + e];
        const float4 xr = *(const float4*)&x[((size_t)b * S_ + s) * E_ + e];
        y.x += bb.x + xr.x; y.y += bb.y + xr.y;
        y.z += bb.z + xr.z; y.w += bb.w + xr.w;
    }

    float sum = y.x + y.y + y.z + y.w;
    float sq  = y.x * y.x + y.y * y.y + y.z * y.z + y.w * y.w;

#pragma unroll
    for (int o = 16; o > 0; o >>= 1) {
        sum += __shfl_xor_sync(0xFFFFFFFFu, sum, o);
        sq  += __shfl_xor_sync(0xFFFFFFFFu, sq, o);
    }
    __shared__ float ssum[4], ssq[4];
    const int wid = tid >> 5, lane = tid & 31;
    if (lane == 0) { ssum[wid] = sum; ssq[wid] = sq; }
    __syncthreads();
    sum = ssum[0] + ssum[1] + ssum[2] + ssum[3];
    sq  = ssq[0] + ssq[1] + ssq[2] + ssq[3];

    const float mu  = sum * (1.0f / E_);
    const float var = sq * (1.0f / E_) - mu * mu;
    const float inv = rsqrtf(var + 1e-5f);

    const float4 g  = *(const float4*)&gamma[e];
    const float4 bt = *(const float4*)&beta[e];
    float4 o;
    o.x = (y.x - mu) * inv * g.x + bt.x;
    o.y = (y.y - mu) * inv * g.y + bt.y;
    o.z = (y.z - mu) * inv * g.z + bt.z;
    o.w = (y.w - mu) * inv * g.w + bt.w;
    *(float4*)&out[((size_t)b * S_ + s) * E_ + e] = o;
}

// ---------------------------------------------------------------------------
extern "C" void kernel_launch(void* const* d_in, const int* in_sizes, int n_in,
                              void* d_out, int out_size)
{
    const float* x     = (const float*)d_in[0];
    const float* W1    = (const float*)d_in[1];
    const float* b1    = (const float*)d_in[2];
    const float* W2    = (const float*)d_in[3];
    const float* b2    = (const float*)d_in[4];
    const float* gamma = (const float*)d_in[5];
    const float* beta  = (const float*)d_in[6];
    float* out = (float*)d_out;

    gemm1_kernel<<<dim3(F_ / 512, S_), 256>>>(x, W1, b1);
    gemm2_kernel<<<dim3(S_, KSPLIT), 256>>>(W2);
    ln_kernel<<<B_ * S_, 128>>>(x, b2, gamma, beta, out);
}

// round 7
// speedup vs baseline: 2.0174x; 2.0174x over previous
#include <cuda_runtime.h>
#include <cstdint>

#define B_ 32
#define S_ 128
#define E_ 512
#define F_ 2048
#define KSPLIT 4

#define NT   256            // CTA N tile
#define KC   32             // K chunk
#define NKC  16             // chunks per CTA (512/32, both gemms)
#define AST  36             // A smem row stride (floats) -> conflict-free frags
#define BST  264            // B smem row stride (floats) -> conflict-free frags
#define ASZ  (32 * AST)     // 1152 floats
#define BSZ  (KC * BST)     // 8448 floats
#define STG  (ASZ + BSZ)    // 9600 floats per stage
#define SMEM_BYTES (2 * STG * 4)   // 76800 B
#define YST  260            // epilogue transpose buffer stride

// Scratch (device globals: allocation-free)
__device__ float g_H [(size_t)S_ * B_ * F_];              // H[s][b][f]
__device__ float g_Yp[(size_t)KSPLIT * S_ * B_ * E_];     // Yp[kp][s][b][e]

__device__ __forceinline__ float to_tf32(float x) {
    float r; asm("cvt.rna.tf32.f32 %0, %1;" : "=f"(r) : "f"(x)); return r;
}
__device__ __forceinline__ float4 cvt4(float4 v) {
    v.x = to_tf32(v.x); v.y = to_tf32(v.y);
    v.z = to_tf32(v.z); v.w = to_tf32(v.w);
    return v;
}

#define MMA_TF32(ac, a, b)                                                  \
    asm volatile(                                                           \
        "mma.sync.aligned.m16n8k8.row.col.f32.tf32.tf32.f32 "               \
        "{%0,%1,%2,%3}, {%4,%5,%6,%7}, {%8,%9}, {%0,%1,%2,%3};"             \
        : "+f"((ac)[0]), "+f"((ac)[1]), "+f"((ac)[2]), "+f"((ac)[3])        \
        : "r"((a)[0]), "r"((a)[1]), "r"((a)[2]), "r"((a)[3]),               \
          "r"((b)[0]), "r"((b)[1]))

// ---------------------------------------------------------------------------
// Unified GEMM.
// MODE 0: H[s][b][f] = sum_e x[b][s][e]*W1[s][e][f] + b1[s][f]
//         grid (F/256, S). K = E = 512.
// MODE 1: Yp[kp][s][b][e] = sum_{f in slice kp} H[s][b][f]*W2[s][f][e]
//         grid (E/256, S, KSPLIT). K = F/KSPLIT = 512.
// CTA: 256 thr, 8 warps. CTA tile M=32 x N=256, warp tile 32x32.
// ---------------------------------------------------------------------------
template <int MODE>
__global__ __launch_bounds__(256, 2)
void gemm_kernel(const float* __restrict__ X, const float* __restrict__ W,
                 const float* __restrict__ bias)
{
    extern __shared__ float sm[];
    const int tid  = threadIdx.x;
    const int warp = tid >> 5, lane = tid & 31;
    const int g = lane >> 2, t = lane & 3;
    const int wn = warp * 32;
    const int s  = blockIdx.y;
    const int n0 = blockIdx.x * NT;

    const float* Arow; size_t lda;
    const float* Bb;   size_t ldb;
    float* Cb;         size_t ldc;
    const float* bi = nullptr;
    int k0 = 0;
    if (MODE == 0) {
        Arow = X + (size_t)s * E_;             lda = (size_t)S_ * E_;
        Bb   = W + (size_t)s * E_ * F_ + n0;   ldb = F_;
        Cb   = g_H + (size_t)s * B_ * F_ + n0; ldc = F_;
        bi   = bias + (size_t)s * F_ + n0;
    } else {
        const int kp = blockIdx.z;
        k0   = kp * (F_ / KSPLIT);
        Arow = g_H + (size_t)s * B_ * F_;      lda = F_;
        Bb   = W + (size_t)s * F_ * E_ + n0;   ldb = E_;
        Cb   = g_Yp + ((size_t)kp * S_ + s) * B_ * E_ + n0; ldc = E_;
    }

    // producer mapping
    const int am = tid >> 3, akf = tid & 7;                 // A: 32 rows x 8 f4
    const float* Aload = Arow + (size_t)am * lda + k0 + akf * 4;
    const float* Bload = Bb + (size_t)k0 * ldb;
    const int asts = am * AST + akf * 4;
    int bgo[8], bsts[8];
#pragma unroll
    for (int r = 0; r < 8; r++) {
        const int idx = r * 256 + tid;
        const int bk = idx >> 6, bn = (idx & 63) * 4;       // 32 k-rows x 64 f4
        bgo[r]  = bk * (int)ldb + bn;
        bsts[r] = bk * BST + bn;
    }

    float acc[2][4][4];
#pragma unroll
    for (int i = 0; i < 2; i++)
#pragma unroll
        for (int j = 0; j < 4; j++)
#pragma unroll
            for (int c = 0; c < 4; c++) acc[i][j][c] = 0.0f;

    float4 ar, br[8];
    // prefetch + store chunk 0
    ar = cvt4(*(const float4*)Aload);
#pragma unroll
    for (int r = 0; r < 8; r++)
        br[r] = cvt4(*(const float4*)(Bload + bgo[r]));
    {
        float* As = sm;
        float* Bs = sm + ASZ;
        *(float4*)&As[asts] = ar;
#pragma unroll
        for (int r = 0; r < 8; r++) *(float4*)&Bs[bsts[r]] = br[r];
    }
    __syncthreads();

    for (int kc = 0; kc < NKC; kc++) {
        const int cur = kc & 1;
        if (kc + 1 < NKC) {   // issue next chunk's loads (hidden under compute)
            ar = cvt4(*(const float4*)(Aload + (kc + 1) * KC));
#pragma unroll
            for (int r = 0; r < 8; r++)
                br[r] = cvt4(*(const float4*)(Bload + (size_t)(kc + 1) * KC * ldb + bgo[r]));
        }
        const float* As = sm + cur * STG;
        const float* Bs = As + ASZ;
#pragma unroll
        for (int ks = 0; ks < 4; ks++) {
            const int kb = ks * 8;
            uint32_t af[2][4], bf[4][2];
#pragma unroll
            for (int i = 0; i < 2; i++) {
                af[i][0] = __float_as_uint(As[(16 * i + g)     * AST + kb + t]);
                af[i][1] = __float_as_uint(As[(16 * i + 8 + g) * AST + kb + t]);
                af[i][2] = __float_as_uint(As[(16 * i + g)     * AST + kb + t + 4]);
                af[i][3] = __float_as_uint(As[(16 * i + 8 + g) * AST + kb + t + 4]);
            }
#pragma unroll
            for (int j = 0; j < 4; j++) {
                bf[j][0] = __float_as_uint(Bs[(kb + t)     * BST + wn + 8 * j + g]);
                bf[j][1] = __float_as_uint(Bs[(kb + t + 4) * BST + wn + 8 * j + g]);
            }
#pragma unroll
            for (int i = 0; i < 2; i++)
#pragma unroll
                for (int j = 0; j < 4; j++) MMA_TF32(acc[i][j], af[i], bf[j]);
        }
        __syncthreads();
        if (kc + 1 < NKC) {
            float* As2 = sm + (cur ^ 1) * STG;
            float* Bs2 = As2 + ASZ;
            *(float4*)&As2[asts] = ar;
#pragma unroll
            for (int r = 0; r < 8; r++) *(float4*)&Bs2[bsts[r]] = br[r];
            __syncthreads();
        }
    }

    // Epilogue: transpose accs through smem for coalesced stores.
    float* Yb = sm;   // 32 x YST floats = 8320 < STG; safe (synced above)
#pragma unroll
    for (int i = 0; i < 2; i++)
#pragma unroll
        for (int j = 0; j < 4; j++) {
            const int m0 = 16 * i + g, n = wn + 8 * j + 2 * t;
            Yb[m0 * YST + n]           = acc[i][j][0];
            Yb[m0 * YST + n + 1]       = acc[i][j][1];
            Yb[(m0 + 8) * YST + n]     = acc[i][j][2];
            Yb[(m0 + 8) * YST + n + 1] = acc[i][j][3];
        }
    __syncthreads();
#pragma unroll
    for (int r = 0; r < 8; r++) {
        const int idx = r * 256 + tid;
        const int m = idx >> 6, nf = (idx & 63) * 4;
        float4 v = *(const float4*)&Yb[m * YST + nf];
        if (MODE == 0) {
            const float4 bb = *(const float4*)(bi + nf);
            v.x += bb.x; v.y += bb.y; v.z += bb.z; v.w += bb.w;
        }
        *(float4*)(Cb + (size_t)m * ldc + nf) = v;
    }
}

// ---------------------------------------------------------------------------
// LN kernel: y = sum_kp Yp + b2 + x ; out = LayerNorm(y)*gamma + beta
// ---------------------------------------------------------------------------
__global__ __launch_bounds__(128)
void ln_kernel(const float* __restrict__ x,
               const float* __restrict__ b2,
               const float* __restrict__ gamma,
               const float* __restrict__ beta,
               float* __restrict__ out)
{
    const int blk = blockIdx.x;
    const int b   = blk >> 7;
    const int s   = blk & (S_ - 1);
    const int tid = threadIdx.x;
    const int e   = tid * 4;

    float4 y = *(const float4*)&g_Yp[(((size_t)0 * S_ + s) * B_ + b) * E_ + e];
#pragma unroll
    for (int kp = 1; kp < KSPLIT; kp++) {
        const float4 p = *(const float4*)&g_Yp[(((size_t)kp * S_ + s) * B_ + b) * E_ + e];
        y.x += p.x; y.y += p.y; y.z += p.z; y.w += p.w;
    }
    {
        const float4 bb = *(const float4*)&b2[(size_t)s * E_ + e];
        const float4 xr = *(const float4*)&x[((size_t)b * S_ + s) * E_ + e];
        y.x += bb.x + xr.x; y.y += bb.y + xr.y;
        y.z += bb.z + xr.z; y.w += bb.w + xr.w;
    }

    float sum = y.x + y.y + y.z + y.w;
    float sq  = y.x * y.x + y.y * y.y + y.z * y.z + y.w * y.w;
#pragma unroll
    for (int o = 16; o > 0; o >>= 1) {
        sum += __shfl_xor_sync(0xFFFFFFFFu, sum, o);
        sq  += __shfl_xor_sync(0xFFFFFFFFu, sq, o);
    }
    __shared__ float ssum[4], ssq[4];
    const int wid = tid >> 5, lane = tid & 31;
    if (lane == 0) { ssum[wid] = sum; ssq[wid] = sq; }
    __syncthreads();
    sum = ssum[0] + ssum[1] + ssum[2] + ssum[3];
    sq  = ssq[0] + ssq[1] + ssq[2] + ssq[3];

    const float mu  = sum * (1.0f / E_);
    const float var = sq * (1.0f / E_) - mu * mu;
    const float inv = rsqrtf(var + 1e-5f);

    const float4 gm = *(const float4*)&gamma[e];
    const float4 bt = *(const float4*)&beta[e];
    float4 o;
    o.x = (y.x - mu) * inv * gm.x + bt.x;
    o.y = (y.y - mu) * inv * gm.y + bt.y;
    o.z = (y.z - mu) * inv * gm.z + bt.z;
    o.w = (y.w - mu) * inv * gm.w + bt.w;
    *(float4*)&out[((size_t)b * S_ + s) * E_ + e] = o;
}

// ---------------------------------------------------------------------------
extern "C" void kernel_launch(void* const* d_in, const int* in_sizes, int n_in,
                              void* d_out, int out_size)
{
    const float* x     = (const float*)d_in[0];
    const float* W1    = (const float*)d_in[1];
    const float* b1    = (const float*)d_in[2];
    const float* W2    = (const float*)d_in[3];
    const float* b2    = (const float*)d_in[4];
    const float* gamma = (const float*)d_in[5];
    const float* beta  = (const float*)d_in[6];
    float* out = (float*)d_out;

    // Idempotent, host-side only, not a stream op: safe on every call.
    cudaFuncSetAttribute(gemm_kernel<0>,
                         cudaFuncAttributeMaxDynamicSharedMemorySize, SMEM_BYTES);
    cudaFuncSetAttribute(gemm_kernel<1>,
                         cudaFuncAttributeMaxDynamicSharedMemorySize, SMEM_BYTES);

    gemm_kernel<0><<<dim3(F_ / NT, S_), 256, SMEM_BYTES>>>(x, W1, b1);
    gemm_kernel<1><<<dim3(E_ / NT, S_, KSPLIT), 256, SMEM_BYTES>>>(nullptr, W2, nullptr);
    ln_kernel<<<B_ * S_, 128>>>(x, b2, gamma, beta, out);
}

// round 8
// speedup vs baseline: 2.5836x; 1.2807x over previous
#include <cuda_runtime.h>
#include <cstdint>

#define B_ 32
#define S_ 128
#define E_ 512
#define F_ 2048
#define KSPLIT 4

#define NT   256            // CTA N tile
#define KC   32             // K chunk
#define NKC  16             // chunks per CTA (512/32, both gemms)
#define AST  36             // A smem row stride (floats) -> conflict-free frags
#define BST  264            // B smem row stride (floats) -> conflict-free frags
#define ASZ  (32 * AST)     // 1152 floats
#define BSZ  (KC * BST)     // 8448 floats
#define STG  (ASZ + BSZ)    // 9600 floats per stage
#define SMEM_BYTES (2 * STG * 4)   // 76800 B
#define YST  260            // epilogue transpose buffer stride

// Scratch (device globals: allocation-free)
__device__ float g_H [(size_t)S_ * B_ * F_];              // H[s][b][f]
__device__ float g_Yp[(size_t)KSPLIT * S_ * B_ * E_];     // Yp[kp][s][b][e]

__device__ __forceinline__ float to_tf32(float x) {
    float r; asm("cvt.rna.tf32.f32 %0, %1;" : "=f"(r) : "f"(x)); return r;
}
__device__ __forceinline__ uint32_t frag(const float* p) {
    return __float_as_uint(to_tf32(*p));
}
__device__ __forceinline__ uint32_t smem_u32(const void* p) {
    uint32_t a;
    asm("{ .reg .u64 t; cvta.to.shared.u64 t, %1; cvt.u32.u64 %0, t; }"
        : "=r"(a) : "l"(p));
    return a;
}
__device__ __forceinline__ void cp16(uint32_t s, const void* g) {
    asm volatile("cp.async.cg.shared.global [%0], [%1], 16;"
                 :: "r"(s), "l"(g) : "memory");
}
#define CP_COMMIT() asm volatile("cp.async.commit_group;" ::: "memory")
#define CP_WAIT1()  asm volatile("cp.async.wait_group 1;" ::: "memory")
#define CP_WAIT0()  asm volatile("cp.async.wait_group 0;" ::: "memory")

#define MMA_TF32(ac, a, b)                                                  \
    asm volatile(                                                           \
        "mma.sync.aligned.m16n8k8.row.col.f32.tf32.tf32.f32 "               \
        "{%0,%1,%2,%3}, {%4,%5,%6,%7}, {%8,%9}, {%0,%1,%2,%3};"             \
        : "+f"((ac)[0]), "+f"((ac)[1]), "+f"((ac)[2]), "+f"((ac)[3])        \
        : "r"((a)[0]), "r"((a)[1]), "r"((a)[2]), "r"((a)[3]),               \
          "r"((b)[0]), "r"((b)[1]))

// ---------------------------------------------------------------------------
// Unified GEMM (cp.async 2-stage pipeline).
// MODE 0: H[s][b][f] = sum_e x[b][s][e]*W1[s][e][f] + b1[s][f]
//         grid (F/256, S). K = E = 512.
// MODE 1: Yp[kp][s][b][e] = sum_{f in slice kp} H[s][b][f]*W2[s][f][e]
//         grid (E/256, S, KSPLIT). K = F/KSPLIT = 512.
// CTA: 256 thr, 8 warps. CTA tile M=32 x N=256, warp tile 32x32.
// ---------------------------------------------------------------------------
template <int MODE>
__global__ __launch_bounds__(256, 2)
void gemm_kernel(const float* __restrict__ X, const float* __restrict__ W,
                 const float* __restrict__ bias)
{
    extern __shared__ float sm[];
    const uint32_t smb = smem_u32(sm);
    const int tid  = threadIdx.x;
    const int warp = tid >> 5, lane = tid & 31;
    const int g = lane >> 2, t = lane & 3;
    const int wn = warp * 32;
    const int s  = blockIdx.y;
    const int n0 = blockIdx.x * NT;

    const float* Arow; size_t lda;
    const float* Bb;   size_t ldb;
    float* Cb;         size_t ldc;
    const float* bi = nullptr;
    int k0 = 0;
    if (MODE == 0) {
        Arow = X + (size_t)s * E_;             lda = (size_t)S_ * E_;
        Bb   = W + (size_t)s * E_ * F_ + n0;   ldb = F_;
        Cb   = g_H + (size_t)s * B_ * F_ + n0; ldc = F_;
        bi   = bias + (size_t)s * F_ + n0;
    } else {
        const int kp = blockIdx.z;
        k0   = kp * (F_ / KSPLIT);
        Arow = g_H + (size_t)s * B_ * F_;      lda = F_;
        Bb   = W + (size_t)s * F_ * E_ + n0;   ldb = E_;
        Cb   = g_Yp + ((size_t)kp * S_ + s) * B_ * E_ + n0; ldc = E_;
    }

    // producer mapping (cp.async 16B per op)
    const int am = tid >> 3, akf = tid & 7;                 // A: 32 rows x 8 f4
    const float* Aload = Arow + (size_t)am * lda + k0 + akf * 4;
    const float* Bload = Bb + (size_t)k0 * ldb;
    const uint32_t asts = smb + (am * AST + akf * 4) * 4;
    int bgo[8]; uint32_t bsts[8];
#pragma unroll
    for (int r = 0; r < 8; r++) {
        const int idx = r * 256 + tid;
        const int bk = idx >> 6, bn = (idx & 63) * 4;       // 32 k-rows x 64 f4
        bgo[r]  = bk * (int)ldb + bn;
        bsts[r] = smb + (ASZ + bk * BST + bn) * 4;
    }

    auto issue = [&](int kc) {
        const uint32_t off = (kc & 1) * (STG * 4);
        cp16(asts + off, Aload + kc * KC);
        const float* bp = Bload + (size_t)kc * KC * ldb;
#pragma unroll
        for (int r = 0; r < 8; r++) cp16(bsts[r] + off, bp + bgo[r]);
        CP_COMMIT();
    };

    float acc[2][4][4];
#pragma unroll
    for (int i = 0; i < 2; i++)
#pragma unroll
        for (int j = 0; j < 4; j++)
#pragma unroll
            for (int c = 0; c < 4; c++) acc[i][j][c] = 0.0f;

    issue(0);

    for (int kc = 0; kc < NKC; kc++) {
        if (kc + 1 < NKC) { issue(kc + 1); CP_WAIT1(); }
        else             { CP_WAIT0(); }
        __syncthreads();

        const float* As = sm + (kc & 1) * STG;
        const float* Bs = As + ASZ;
#pragma unroll
        for (int ks = 0; ks < 4; ks++) {
            const int kb = ks * 8;
            uint32_t af[2][4], bf[4][2];
#pragma unroll
            for (int i = 0; i < 2; i++) {
                af[i][0] = frag(&As[(16 * i + g)     * AST + kb + t]);
                af[i][1] = frag(&As[(16 * i + 8 + g) * AST + kb + t]);
                af[i][2] = frag(&As[(16 * i + g)     * AST + kb + t + 4]);
                af[i][3] = frag(&As[(16 * i + 8 + g) * AST + kb + t + 4]);
            }
#pragma unroll
            for (int j = 0; j < 4; j++) {
                bf[j][0] = frag(&Bs[(kb + t)     * BST + wn + 8 * j + g]);
                bf[j][1] = frag(&Bs[(kb + t + 4) * BST + wn + 8 * j + g]);
            }
#pragma unroll
            for (int i = 0; i < 2; i++)
#pragma unroll
                for (int j = 0; j < 4; j++) MMA_TF32(acc[i][j], af[i], bf[j]);
        }
        __syncthreads();   // stage (kc&1) free for chunk kc+2
    }

    // Epilogue: transpose accs through smem for coalesced stores.
    float* Yb = sm;   // 32 x YST = 8320 floats < STG; synced above
#pragma unroll
    for (int i = 0; i < 2; i++)
#pragma unroll
        for (int j = 0; j < 4; j++) {
            const int m0 = 16 * i + g, n = wn + 8 * j + 2 * t;
            Yb[m0 * YST + n]           = acc[i][j][0];
            Yb[m0 * YST + n + 1]       = acc[i][j][1];
            Yb[(m0 + 8) * YST + n]     = acc[i][j][2];
            Yb[(m0 + 8) * YST + n + 1] = acc[i][j][3];
        }
    __syncthreads();
#pragma unroll
    for (int r = 0; r < 8; r++) {
        const int idx = r * 256 + tid;
        const int m = idx >> 6, nf = (idx & 63) * 4;
        float4 v = *(const float4*)&Yb[m * YST + nf];
        if (MODE == 0) {
            const float4 bb = *(const float4*)(bi + nf);
            v.x += bb.x; v.y += bb.y; v.z += bb.z; v.w += bb.w;
        }
        *(float4*)(Cb + (size_t)m * ldc + nf) = v;
    }
}

// ---------------------------------------------------------------------------
// LN kernel: y = sum_kp Yp + b2 + x ; out = LayerNorm(y)*gamma + beta
// ---------------------------------------------------------------------------
__global__ __launch_bounds__(128)
void ln_kernel(const float* __restrict__ x,
               const float* __restrict__ b2,
               const float* __restrict__ gamma,
               const float* __restrict__ beta,
               float* __restrict__ out)
{
    const int blk = blockIdx.x;
    const int b   = blk >> 7;
    const int s   = blk & (S_ - 1);
    const int tid = threadIdx.x;
    const int e   = tid * 4;

    float4 y = *(const float4*)&g_Yp[(((size_t)0 * S_ + s) * B_ + b) * E_ + e];
#pragma unroll
    for (int kp = 1; kp < KSPLIT; kp++) {
        const float4 p = *(const float4*)&g_Yp[(((size_t)kp * S_ + s) * B_ + b) * E_ + e];
        y.x += p.x; y.y += p.y; y.z += p.z; y.w += p.w;
    }
    {
        const float4 bb = *(const float4*)&b2[(size_t)s * E_ + e];
        const float4 xr = *(const float4*)&x[((size_t)b * S_ + s) * E_ + e];
        y.x += bb.x + xr.x; y.y += bb.y + xr.y;
        y.z += bb.z + xr.z; y.w += bb.w + xr.w;
    }

    float sum = y.x + y.y + y.z + y.w;
    float sq  = y.x * y.x + y.y * y.y + y.z * y.z + y.w * y.w;
#pragma unroll
    for (int o = 16; o > 0; o >>= 1) {
        sum += __shfl_xor_sync(0xFFFFFFFFu, sum, o);
        sq  += __shfl_xor_sync(0xFFFFFFFFu, sq, o);
    }
    __shared__ float ssum[4], ssq[4];
    const int wid = tid >> 5, lane = tid & 31;
    if (lane == 0) { ssum[wid] = sum; ssq[wid] = sq; }
    __syncthreads();
    sum = ssum[0] + ssum[1] + ssum[2] + ssum[3];
    sq  = ssq[0] + ssq[1] + ssq[2] + ssq[3];

    const float mu  = sum * (1.0f / E_);
    const float var = sq * (1.0f / E_) - mu * mu;
    const float inv = rsqrtf(var + 1e-5f);

    const float4 gm = *(const float4*)&gamma[e];
    const float4 bt = *(const float4*)&beta[e];
    float4 o;
    o.x = (y.x - mu) * inv * gm.x + bt.x;
    o.y = (y.y - mu) * inv * gm.y + bt.y;
    o.z = (y.z - mu) * inv * gm.z + bt.z;
    o.w = (y.w - mu) * inv * gm.w + bt.w;
    *(float4*)&out[((size_t)b * S_ + s) * E_ + e] = o;
}

// ---------------------------------------------------------------------------
extern "C" void kernel_launch(void* const* d_in, const int* in_sizes, int n_in,
                              void* d_out, int out_size)
{
    const float* x     = (const float*)d_in[0];
    const float* W1    = (const float*)d_in[1];
    const float* b1    = (const float*)d_in[2];
    const float* W2    = (const float*)d_in[3];
    const float* b2    = (const float*)d_in[4];
    const float* gamma = (const float*)d_in[5];
    const float* beta  = (const float*)d_in[6];
    float* out = (float*)d_out;

    // Idempotent, host-side only, not a stream op: safe on every call.
    cudaFuncSetAttribute(gemm_kernel<0>,
                         cudaFuncAttributeMaxDynamicSharedMemorySize, SMEM_BYTES);
    cudaFuncSetAttribute(gemm_kernel<1>,
                         cudaFuncAttributeMaxDynamicSharedMemorySize, SMEM_BYTES);

    gemm_kernel<0><<<dim3(F_ / NT, S_), 256, SMEM_BYTES>>>(x, W1, b1);
    gemm_kernel<1><<<dim3(E_ / NT, S_, KSPLIT), 256, SMEM_BYTES>>>(nullptr, W2, nullptr);
    ln_kernel<<<B_ * S_, 128>>>(x, b2, gamma, beta, out);
}

// round 9
// speedup vs baseline: 2.5994x; 1.0061x over previous
#include <cuda_runtime.h>
#include <cstdint>

#define B_ 32
#define S_ 128
#define E_ 512
#define F_ 2048

#define KC   32             // K chunk (both kernels)
#define AST  36             // A smem row stride (floats), conflict-free frags

// ---- gemm1 (unchanged from R8): CTA 256 thr, M=32 x N=256 ----
#define NT1  256
#define NKC1 16
#define BST1 264
#define ASZ1 (32 * AST)          // 1152
#define BSZ1 (KC * BST1)         // 8448
#define STG1 (ASZ1 + BSZ1)       // 9600 floats
#define SMEM1 (2 * STG1 * 4)     // 76800 B
#define YST1 260

// ---- gemm2 fused: CTA 512 thr, M=32 x N=512, K=2048, 3-stage ----
#define NKC2 64
#define BST2 520
#define ASZ2 (32 * AST)          // 1152
#define BSZ2 (KC * BST2)         // 16640
#define STG2 (ASZ2 + BSZ2)       // 17792 floats
#define SMEM2 (3 * STG2 * 4)     // 213504 B

// Scratch (device global: allocation-free)
__device__ float g_H[(size_t)S_ * B_ * F_];   // H[s][b][f]

__device__ __forceinline__ float to_tf32(float x) {
    float r; asm("cvt.rna.tf32.f32 %0, %1;" : "=f"(r) : "f"(x)); return r;
}
__device__ __forceinline__ uint32_t frag(const float* p) {
    return __float_as_uint(to_tf32(*p));
}
__device__ __forceinline__ uint32_t smem_u32(const void* p) {
    uint32_t a;
    asm("{ .reg .u64 t; cvta.to.shared.u64 t, %1; cvt.u32.u64 %0, t; }"
        : "=r"(a) : "l"(p));
    return a;
}
__device__ __forceinline__ void cp16(uint32_t s, const void* g) {
    asm volatile("cp.async.cg.shared.global [%0], [%1], 16;"
                 :: "r"(s), "l"(g) : "memory");
}
#define CP_COMMIT() asm volatile("cp.async.commit_group;" ::: "memory")
#define CP_WAIT1()  asm volatile("cp.async.wait_group 1;" ::: "memory")
#define CP_WAIT0()  asm volatile("cp.async.wait_group 0;" ::: "memory")

#define MMA_TF32(ac, a, b)                                                  \
    asm volatile(                                                           \
        "mma.sync.aligned.m16n8k8.row.col.f32.tf32.tf32.f32 "               \
        "{%0,%1,%2,%3}, {%4,%5,%6,%7}, {%8,%9}, {%0,%1,%2,%3};"             \
        : "+f"((ac)[0]), "+f"((ac)[1]), "+f"((ac)[2]), "+f"((ac)[3])        \
        : "r"((a)[0]), "r"((a)[1]), "r"((a)[2]), "r"((a)[3]),               \
          "r"((b)[0]), "r"((b)[1]))

// ---------------------------------------------------------------------------
// GEMM1 (identical structure to R8 MODE 0):
// H[s][b][f] = sum_e x[b][s][e]*W1[s][e][f] + b1[s][f]
// grid (F/256, S), 256 thr, 2-stage cp.async.
// ---------------------------------------------------------------------------
__global__ __launch_bounds__(256, 2)
void gemm1_kernel(const float* __restrict__ X, const float* __restrict__ W,
                  const float* __restrict__ bias)
{
    extern __shared__ float sm[];
    const uint32_t smb = smem_u32(sm);
    const int tid  = threadIdx.x;
    const int warp = tid >> 5, lane = tid & 31;
    const int g = lane >> 2, t = lane & 3;
    const int wn = warp * 32;
    const int s  = blockIdx.y;
    const int n0 = blockIdx.x * NT1;

    const float* Arow = X + (size_t)s * E_;           const size_t lda = (size_t)S_ * E_;
    const float* Bb   = W + (size_t)s * E_ * F_ + n0; const size_t ldb = F_;
    float* Cb = g_H + (size_t)s * B_ * F_ + n0;       const size_t ldc = F_;
    const float* bi = bias + (size_t)s * F_ + n0;

    const int am = tid >> 3, akf = tid & 7;           // A: 32 rows x 8 f4
    const float* Aload = Arow + (size_t)am * lda + akf * 4;
    const uint32_t asts = smb + (am * AST + akf * 4) * 4;
    int bgo[8]; uint32_t bsts[8];
#pragma unroll
    for (int r = 0; r < 8; r++) {
        const int idx = r * 256 + tid;
        const int bk = idx >> 6, bn = (idx & 63) * 4; // 32 k-rows x 64 f4
        bgo[r]  = bk * (int)ldb + bn;
        bsts[r] = smb + (ASZ1 + bk * BST1 + bn) * 4;
    }

    auto issue = [&](int kc) {
        const uint32_t off = (kc & 1) * (STG1 * 4);
        cp16(asts + off, Aload + kc * KC);
        const float* bp = Bb + (size_t)kc * KC * ldb;
#pragma unroll
        for (int r = 0; r < 8; r++) cp16(bsts[r] + off, bp + bgo[r]);
        CP_COMMIT();
    };

    float acc[2][4][4];
#pragma unroll
    for (int i = 0; i < 2; i++)
#pragma unroll
        for (int j = 0; j < 4; j++)
#pragma unroll
            for (int c = 0; c < 4; c++) acc[i][j][c] = 0.0f;

    issue(0);
    for (int kc = 0; kc < NKC1; kc++) {
        if (kc + 1 < NKC1) { issue(kc + 1); CP_WAIT1(); }
        else               { CP_WAIT0(); }
        __syncthreads();
        const float* As = sm + (kc & 1) * STG1;
        const float* Bs = As + ASZ1;
#pragma unroll
        for (int ks = 0; ks < 4; ks++) {
            const int kb = ks * 8;
            uint32_t af[2][4], bf[4][2];
#pragma unroll
            for (int i = 0; i < 2; i++) {
                af[i][0] = frag(&As[(16 * i + g)     * AST + kb + t]);
                af[i][1] = frag(&As[(16 * i + 8 + g) * AST + kb + t]);
                af[i][2] = frag(&As[(16 * i + g)     * AST + kb + t + 4]);
                af[i][3] = frag(&As[(16 * i + 8 + g) * AST + kb + t + 4]);
            }
#pragma unroll
            for (int j = 0; j < 4; j++) {
                bf[j][0] = frag(&Bs[(kb + t)     * BST1 + wn + 8 * j + g]);
                bf[j][1] = frag(&Bs[(kb + t + 4) * BST1 + wn + 8 * j + g]);
            }
#pragma unroll
            for (int i = 0; i < 2; i++)
#pragma unroll
                for (int j = 0; j < 4; j++) MMA_TF32(acc[i][j], af[i], bf[j]);
        }
        __syncthreads();
    }

    float* Yb = sm;
#pragma unroll
    for (int i = 0; i < 2; i++)
#pragma unroll
        for (int j = 0; j < 4; j++) {
            const int m0 = 16 * i + g, n = wn + 8 * j + 2 * t;
            Yb[m0 * YST1 + n]           = acc[i][j][0];
            Yb[m0 * YST1 + n + 1]       = acc[i][j][1];
            Yb[(m0 + 8) * YST1 + n]     = acc[i][j][2];
            Yb[(m0 + 8) * YST1 + n + 1] = acc[i][j][3];
        }
    __syncthreads();
#pragma unroll
    for (int r = 0; r < 8; r++) {
        const int idx = r * 256 + tid;
        const int m = idx >> 6, nf = (idx & 63) * 4;
        float4 v = *(const float4*)&Yb[m * YST1 + nf];
        const float4 bb = *(const float4*)(bi + nf);
        v.x += bb.x; v.y += bb.y; v.z += bb.z; v.w += bb.w;
        *(float4*)(Cb + (size_t)m * ldc + nf) = v;
    }
}

// ---------------------------------------------------------------------------
// GEMM2 fused: out[b][s][:] = LN( H[s][b][:] @ W2[s] + b2[s] + x[b][s][:] )
// grid (S) = 128 CTAs, 512 thr / 16 warps. M=32 x N=512, K=2048,
// 3-stage cp.async (depth-2 in flight), LN fused in epilogue.
// ---------------------------------------------------------------------------
__global__ __launch_bounds__(512, 1)
void gemm2_fused(const float* __restrict__ x, const float* __restrict__ W2,
                 const float* __restrict__ b2, const float* __restrict__ gamma,
                 const float* __restrict__ beta, float* __restrict__ out)
{
    extern __shared__ float sm[];
    const uint32_t smb = smem_u32(sm);
    const int tid  = threadIdx.x;
    const int warp = tid >> 5, lane = tid & 31;
    const int g = lane >> 2, t = lane & 3;
    const int wn = warp * 32;           // warp covers n in [wn, wn+32)
    const int s = blockIdx.x;

    const float* Arow = g_H + (size_t)s * B_ * F_;   // lda = F_
    const float* Bb   = W2 + (size_t)s * F_ * E_;    // ldb = E_

    // producers: A by threads 0..255 (32 rows x 8 f4), B by all (8 f4 each)
    const int am = tid >> 3, akf = tid & 7;
    const float* Aload = Arow + (size_t)am * F_ + akf * 4;
    const uint32_t asts = smb + (am * AST + akf * 4) * 4;
    int bgo[8]; uint32_t bsts[8];
#pragma unroll
    for (int r = 0; r < 8; r++) {
        const int idx = r * 512 + tid;                // 0..4095
        const int bk = idx >> 7, bn = (idx & 127) * 4; // 32 k-rows x 128 f4
        bgo[r]  = bk * E_ + bn;
        bsts[r] = smb + (ASZ2 + bk * BST2 + bn) * 4;
    }

    auto issue = [&](int kc) {
        const uint32_t off = (uint32_t)(kc % 3) * (STG2 * 4);
        if (tid < 256) cp16(asts + off, Aload + kc * KC);
        const float* bp = Bb + (size_t)kc * KC * E_;
#pragma unroll
        for (int r = 0; r < 8; r++) cp16(bsts[r] + off, bp + bgo[r]);
        CP_COMMIT();
    };

    float acc[2][4][4];
#pragma unroll
    for (int i = 0; i < 2; i++)
#pragma unroll
        for (int j = 0; j < 4; j++)
#pragma unroll
            for (int c = 0; c < 4; c++) acc[i][j][c] = 0.0f;

    issue(0);
    issue(1);
    for (int kc = 0; kc < NKC2; kc++) {
        if (kc + 1 < NKC2) CP_WAIT1(); else CP_WAIT0();
        __syncthreads();
        // stage (kc+2)%3 == (kc-1)%3 was fully consumed before this barrier
        if (kc + 2 < NKC2) issue(kc + 2);

        const float* As = sm + (kc % 3) * STG2;
        const float* Bs = As + ASZ2;
#pragma unroll
        for (int ks = 0; ks < 4; ks++) {
            const int kb = ks * 8;
            uint32_t af[2][4], bf[4][2];
#pragma unroll
            for (int i = 0; i < 2; i++) {
                af[i][0] = frag(&As[(16 * i + g)     * AST + kb + t]);
                af[i][1] = frag(&As[(16 * i + 8 + g) * AST + kb + t]);
                af[i][2] = frag(&As[(16 * i + g)     * AST + kb + t + 4]);
                af[i][3] = frag(&As[(16 * i + 8 + g) * AST + kb + t + 4]);
            }
#pragma unroll
            for (int j = 0; j < 4; j++) {
                bf[j][0] = frag(&Bs[(kb + t)     * BST2 + wn + 8 * j + g]);
                bf[j][1] = frag(&Bs[(kb + t + 4) * BST2 + wn + 8 * j + g]);
            }
#pragma unroll
            for (int i = 0; i < 2; i++)
#pragma unroll
                for (int j = 0; j < 4; j++) MMA_TF32(acc[i][j], af[i], bf[j]);
        }
        __syncthreads();
    }

    // ---- Epilogue: transpose to smem, then per-row LayerNorm ----
    float* Yb = sm;   // 32 x BST2 floats = 66.5 KB, all cp.async drained
#pragma unroll
    for (int i = 0; i < 2; i++)
#pragma unroll
        for (int j = 0; j < 4; j++) {
            const int m0 = 16 * i + g, n = wn + 8 * j + 2 * t;
            Yb[m0 * BST2 + n]           = acc[i][j][0];
            Yb[m0 * BST2 + n + 1]       = acc[i][j][1];
            Yb[(m0 + 8) * BST2 + n]     = acc[i][j][2];
            Yb[(m0 + 8) * BST2 + n + 1] = acc[i][j][3];
        }
    __syncthreads();

    // warp w handles batch rows 2w and 2w+1; lane covers e = lane + 32*i
#pragma unroll
    for (int rr = 0; rr < 2; rr++) {
        const int m = warp * 2 + rr;
        const float* xr = x + ((size_t)m * S_ + s) * E_;
        const float* bb = b2 + (size_t)s * E_;
        float v[16];
        float sum = 0.0f, sq = 0.0f;
#pragma unroll
        for (int i = 0; i < 16; i++) {
            const int e = lane + 32 * i;
            const float y = Yb[m * BST2 + e] + bb[e] + xr[e];
            v[i] = y;
            sum += y; sq += y * y;
        }
#pragma unroll
        for (int o = 16; o > 0; o >>= 1) {
            sum += __shfl_xor_sync(0xFFFFFFFFu, sum, o);
            sq  += __shfl_xor_sync(0xFFFFFFFFu, sq, o);
        }
        const float mu  = sum * (1.0f / E_);
        const float var = sq * (1.0f / E_) - mu * mu;
        const float inv = rsqrtf(var + 1e-5f);
        float* orow = out + ((size_t)m * S_ + s) * E_;
#pragma unroll
        for (int i = 0; i < 16; i++) {
            const int e = lane + 32 * i;
            orow[e] = (v[i] - mu) * inv * gamma[e] + beta[e];
        }
    }
}

// ---------------------------------------------------------------------------
extern "C" void kernel_launch(void* const* d_in, const int* in_sizes, int n_in,
                              void* d_out, int out_size)
{
    const float* x     = (const float*)d_in[0];
    const float* W1    = (const float*)d_in[1];
    const float* b1    = (const float*)d_in[2];
    const float* W2    = (const float*)d_in[3];
    const float* b2    = (const float*)d_in[4];
    const float* gamma = (const float*)d_in[5];
    const float* beta  = (const float*)d_in[6];
    float* out = (float*)d_out;

    // Idempotent, host-side only, not a stream op: safe on every call.
    cudaFuncSetAttribute(gemm1_kernel,
                         cudaFuncAttributeMaxDynamicSharedMemorySize, SMEM1);
    cudaFuncSetAttribute(gemm2_fused,
                         cudaFuncAttributeMaxDynamicSharedMemorySize, SMEM2);

    gemm1_kernel<<<dim3(F_ / NT1, S_), 256, SMEM1>>>(x, W1, b1);
    gemm2_fused<<<S_, 512, SMEM2>>>(x, W2, b2, gamma, beta, out);
}